// round 2
// baseline (speedup 1.0000x reference)
#include <cuda_runtime.h>

#define NN   4096
#define BB   8
#define FIN  40
#define HH   64
#define KK   5
#define LL   4092   // N - K + 1

#define RC1  64     // row chunks, kernel 1 (64 rows each)
#define CB1  8      // col blocks (512 cols each)
#define RC2  32     // row chunks, kernel 2 (128 rows each)
#define CB2  8
#define MC3  16     // m-chunks, kernel 3 (256 m each)

// ---- scratch (static device memory; every element rewritten each launch) ----
__device__ float d_Tpart[RC1][NN];            // partial column sums of A
__device__ float d_gint[NN * 8];              // g_k[m], interleaved [m][8] (k=0..4 used)
__device__ float d_cpart[RC2][KK][NN];        // partial c_k[m]
__device__ float d_c[KK][NN];                 // c_k[m], planar
__device__ float d_ppart[BB][MC3][KK][FIN];   // partial p_k[b][f]

// ============================================================
// Kernel 1: partial column sums of A.  T_part[rc][m] = sum of 64 rows.
// grid (CB1, RC1) = 512 blocks, 128 threads, float4 loads (coalesced).
// ============================================================
__global__ void k1_colsum(const float* __restrict__ A) {
    const int c4 = blockIdx.x * 128 + threadIdx.x;     // float4 col index
    const int n0 = blockIdx.y * (NN / RC1);
    const float4* Ap = reinterpret_cast<const float4*>(A);
    float4 acc = make_float4(0.f, 0.f, 0.f, 0.f);
#pragma unroll 8
    for (int n = n0; n < n0 + NN / RC1; n++) {
        float4 a = __ldg(&Ap[n * (NN / 4) + c4]);
        acc.x += a.x; acc.y += a.y; acc.z += a.z; acc.w += a.w;
    }
    *reinterpret_cast<float4*>(&d_Tpart[blockIdx.y][c4 * 4]) = acc;
}

// ============================================================
// Kernel 2 (fused): recompute g for this 128-row strip from Tpart + A edge
// rows, then c partials: c_part[rc][k][m] = sum_{n in strip} A[n,m]*g_k[n].
// grid (CB2, RC2) = 256 blocks, 128 threads.
// Column-block 0 additionally writes d_gint for k4's sg reduction.
// ============================================================
__global__ void k2_cpart(const float* __restrict__ A) {
    __shared__ float gsk[KK][128];
    const int tid = threadIdx.x;
    const int c4  = blockIdx.x * 128 + tid;            // float4 col index
    const int n0  = blockIdx.y * 128;

    // --- inline g computation for row n = n0 + tid ---
    {
        const int n = n0 + tid;
        float T = 0.f;
#pragma unroll
        for (int r = 0; r < RC1; r++) T += d_Tpart[r][n];

        float top[4], bot[4];
#pragma unroll
        for (int j = 0; j < 4; j++) top[j] = __ldg(&A[j * NN + n]);
#pragma unroll
        for (int j = 0; j < 4; j++) bot[j] = __ldg(&A[(4092 + j) * NN + n]);

        float g[KK];
        float cumtop = 0.f;
#pragma unroll
        for (int k = 0; k < KK; k++) {
            float sb = 0.f;
#pragma unroll
            for (int j = 0; j < 4; j++) if (j >= k) sb += bot[j];
            g[k] = T - cumtop - sb;
            if (k < 4) cumtop += top[k];
        }
#pragma unroll
        for (int k = 0; k < KK; k++) gsk[k][tid] = g[k];

        if (blockIdx.x == 0) {
            float4* gp = reinterpret_cast<float4*>(&d_gint[n * 8]);
            gp[0] = make_float4(g[0], g[1], g[2], g[3]);
            gp[1] = make_float4(g[4], 0.f, 0.f, 0.f);
        }
    }
    __syncthreads();

    // --- main accumulation over the 128-row strip ---
    float4 acc[KK];
#pragma unroll
    for (int k = 0; k < KK; k++) acc[k] = make_float4(0.f, 0.f, 0.f, 0.f);

    const float4* Ap = reinterpret_cast<const float4*>(A);
#pragma unroll 8
    for (int nl = 0; nl < 128; nl++) {
        float4 a  = __ldg(&Ap[(n0 + nl) * (NN / 4) + c4]);
        float g0 = gsk[0][nl], g1 = gsk[1][nl], g2 = gsk[2][nl];
        float g3 = gsk[3][nl], g4 = gsk[4][nl];
        acc[0].x += a.x * g0; acc[0].y += a.y * g0; acc[0].z += a.z * g0; acc[0].w += a.w * g0;
        acc[1].x += a.x * g1; acc[1].y += a.y * g1; acc[1].z += a.z * g1; acc[1].w += a.w * g1;
        acc[2].x += a.x * g2; acc[2].y += a.y * g2; acc[2].z += a.z * g2; acc[2].w += a.w * g2;
        acc[3].x += a.x * g3; acc[3].y += a.y * g3; acc[3].z += a.z * g3; acc[3].w += a.w * g3;
        acc[4].x += a.x * g4; acc[4].y += a.y * g4; acc[4].z += a.z * g4; acc[4].w += a.w * g4;
    }
#pragma unroll
    for (int k = 0; k < KK; k++)
        *reinterpret_cast<float4*>(&d_cpart[blockIdx.y][k][c4 * 4]) = acc[k];
}

// ============================================================
// Kernel 2b: combine c partials into planar d_c[k][m].
// grid (16, KK) = 80 blocks, 256 threads, one m per thread.
// ============================================================
__global__ void k2b_combine_c() {
    const int m = blockIdx.x * blockDim.x + threadIdx.x;
    const int k = blockIdx.y;
    float s = 0.f;
#pragma unroll
    for (int r = 0; r < RC2; r++) s += d_cpart[r][k][m];
    d_c[k][m] = s;
}

// ============================================================
// Kernel 3: p_k[b][f] partials = sum_m c_k[m] * x[b][m][f].
// grid (MC3, BB), 320 threads: f = t%40, gl = t/40.
// ============================================================
__global__ void k3_ppart(const float* __restrict__ x) {
    const int b  = blockIdx.y;
    const int mc = blockIdx.x;
    const int t  = threadIdx.x;
    const int f  = t % FIN;
    const int gl = t / FIN;            // 0..7
    const int mbase = mc * (NN / MC3); // 256-m chunk

    const float* xb = x + (size_t)b * NN * FIN;
    float acc[KK] = {0.f, 0.f, 0.f, 0.f, 0.f};
#pragma unroll 4
    for (int j = 0; j < (NN / MC3) / 8; j++) {   // 32 iters
        int m = mbase + gl + 8 * j;
        float xv = __ldg(&xb[m * FIN + f]);
        float c0 = __ldg(&d_c[0][m]);
        float c1 = __ldg(&d_c[1][m]);
        float c2 = __ldg(&d_c[2][m]);
        float c3 = __ldg(&d_c[3][m]);
        float c4 = __ldg(&d_c[4][m]);
        acc[0] += xv * c0; acc[1] += xv * c1; acc[2] += xv * c2;
        acc[3] += xv * c3; acc[4] += xv * c4;
    }

    __shared__ float ps[8][KK][FIN];
#pragma unroll
    for (int k = 0; k < KK; k++) ps[gl][k][f] = acc[k];
    __syncthreads();

    if (t < KK * FIN) {
        int k = t / FIN, ff = t % FIN;
        float s = 0.f;
#pragma unroll
        for (int g = 0; g < 8; g++) s += ps[g][k][ff];
        d_ppart[b][mc][k][ff] = s;
    }
}

// ============================================================
// Kernel 4: fold everything into out[b].
//   q[i][k]  = sum_o fc_w[o] * conv_w[o][i][k]
//   r[k][h]  = sum_i W2[h][i] * q[i][k]
//   s[k][f]  = sum_h W1[f][h] * r[k][h];  t[k] = sum_h b1[h] r[k][h]
//   out[b]   = (1/L)(sum_{k,f} p_k[b][f] s[k][f] + sum_k sg_k t[k])
//              + sum_{i,k} q[i][k] b2[i] + sum_o fc_w[o] conv_b[o] + fc_b
// ============================================================
__global__ void k4_final(const float* __restrict__ W1, const float* __restrict__ b1,
                         const float* __restrict__ W2, const float* __restrict__ b2,
                         const float* __restrict__ cw, const float* __restrict__ cb,
                         const float* __restrict__ fw, const float* __restrict__ fb,
                         float* __restrict__ out) {
    __shared__ float q_s[HH][KK];
    __shared__ float r_s[KK][HH];
    __shared__ float s_s[KK][FIN];
    __shared__ float sg_s[KK];
    __shared__ float t_s[KK];
    __shared__ float p_s[KK][BB][FIN];
    __shared__ float red[256];
    __shared__ float misc[2];
    const int t = threadIdx.x;   // 256 threads

    // q
    for (int idx = t; idx < HH * KK; idx += 256) {
        int i = idx / KK, k = idx % KK;
        float s = 0.f;
        for (int o = 0; o < HH; o++) s += __ldg(&fw[o]) * __ldg(&cw[(o * HH + i) * KK + k]);
        q_s[i][k] = s;
    }
    // p reduce over m-chunks
    for (int idx = t; idx < KK * BB * FIN; idx += 256) {
        int k = idx / (BB * FIN);
        int rem = idx % (BB * FIN);
        int b = rem / FIN, f = rem % FIN;
        float s = 0.f;
#pragma unroll
        for (int mc = 0; mc < MC3; mc++) s += d_ppart[b][mc][k][f];
        p_s[k][b][f] = s;
    }
    // sg_k = sum_m g_k[m]  (fixed-order tree reduction -> deterministic)
    {
        float part[KK] = {0.f, 0.f, 0.f, 0.f, 0.f};
        for (int m = t; m < NN; m += 256) {
#pragma unroll
            for (int k = 0; k < KK; k++) part[k] += d_gint[m * 8 + k];
        }
        for (int k = 0; k < KK; k++) {
            red[t] = part[k];
            __syncthreads();
            for (int ofs = 128; ofs > 0; ofs >>= 1) {
                if (t < ofs) red[t] += red[t + ofs];
                __syncthreads();
            }
            if (t == 0) sg_s[k] = red[0];
            __syncthreads();
        }
    }
    __syncthreads();   // q_s, p_s complete

    // r
    for (int idx = t; idx < KK * HH; idx += 256) {
        int k = idx / HH, h = idx % HH;
        float s = 0.f;
        for (int i = 0; i < HH; i++) s += __ldg(&W2[h * HH + i]) * q_s[i][k];
        r_s[k][h] = s;
    }
    __syncthreads();

    // s, t
    for (int idx = t; idx < KK * FIN; idx += 256) {
        int k = idx / FIN, f = idx % FIN;
        float s = 0.f;
        for (int h = 0; h < HH; h++) s += __ldg(&W1[f * HH + h]) * r_s[k][h];
        s_s[k][f] = s;
    }
    if (t < KK) {
        float s = 0.f;
        for (int h = 0; h < HH; h++) s += __ldg(&b1[h]) * r_s[t][h];
        t_s[t] = s;
    }
    if (t == 0) {
        float bias2 = 0.f;
        for (int i = 0; i < HH; i++)
            for (int k = 0; k < KK; k++) bias2 += q_s[i][k] * __ldg(&b2[i]);
        float C0 = __ldg(&fb[0]);
        for (int o = 0; o < HH; o++) C0 += __ldg(&fw[o]) * __ldg(&cb[o]);
        misc[0] = bias2;
        misc[1] = C0;
    }
    __syncthreads();

    if (t < BB) {
        float acc = 0.f;
        for (int k = 0; k < KK; k++) {
            float a = 0.f;
            for (int f = 0; f < FIN; f++) a += p_s[k][t][f] * s_s[k][f];
            acc += a + sg_s[k] * t_s[k];
        }
        out[t] = acc * (1.0f / (float)LL) + misc[0] + misc[1];
    }
}

// ============================================================
extern "C" void kernel_launch(void* const* d_in, const int* in_sizes, int n_in,
                              void* d_out, int out_size) {
    const float* x   = (const float*)d_in[0];
    const float* A   = (const float*)d_in[1];
    const float* W1  = (const float*)d_in[2];
    const float* b1  = (const float*)d_in[3];
    const float* W2  = (const float*)d_in[4];
    const float* b2  = (const float*)d_in[5];
    const float* cw  = (const float*)d_in[6];
    const float* cb  = (const float*)d_in[7];
    const float* fw  = (const float*)d_in[8];
    const float* fb  = (const float*)d_in[9];
    float* out = (float*)d_out;

    k1_colsum<<<dim3(CB1, RC1), 128>>>(A);
    k2_cpart<<<dim3(CB2, RC2), 128>>>(A);
    k2b_combine_c<<<dim3(16, KK), 256>>>();
    k3_ppart<<<dim3(MC3, BB), 320>>>(x);
    k4_final<<<1, 256>>>(W1, b1, W2, b2, cw, cb, fw, fb, out);
}

// round 3
// speedup vs baseline: 1.1501x; 1.1501x over previous
#include <cuda_runtime.h>

#define NN   4096
#define BB   8
#define FIN  40
#define HH   64
#define KK   5
#define LL   4092   // N - K + 1

#define RC1  128    // row chunks, kernel 1 (32 rows each)
#define RC2  64     // row chunks, kernel 2 (64 rows each)
#define YC   32     // y chunks in k3

// ---- scratch (static device memory; every element rewritten each launch) ----
__device__ float d_Tpart[RC1][NN];          // partial column sums of A
__device__ float d_cpart[RC2][KK][NN];      // partial c_k[m]
__device__ float d_g[KK][NN];               // g_k[n]
__device__ float d_u[NN * FIN];             // u[m][f] = sum_k s[k][f] c_k[m]
__device__ float d_ypart[BB * YC];          // partial dot products
__device__ float d_sfk[KK][FIN];            // folded weight vector s[k][f]
__device__ float d_tk[KK];                  // t[k] = b1 . r[k]
__device__ float d_misc[2];                 // bias2, C0

// ============================================================
// Kernel 0: fold weights (independent of A, x).
//   q[i][k] = sum_o fc_w[o] conv_w[o][i][k]
//   r[k][h] = sum_i W2[h][i] q[i][k]
//   s[k][f] = sum_h W1[f][h] r[k][h];   t[k] = sum_h b1[h] r[k][h]
//   misc[0] = sum_{i,k} q[i][k] b2[i];  misc[1] = fc_w.conv_b + fc_b
// ============================================================
__global__ void k0_prep(const float* __restrict__ W1, const float* __restrict__ b1,
                        const float* __restrict__ W2, const float* __restrict__ b2,
                        const float* __restrict__ cw, const float* __restrict__ cb,
                        const float* __restrict__ fw, const float* __restrict__ fb) {
    __shared__ float q_s[HH][KK];
    __shared__ float r_s[KK][HH];
    const int t = threadIdx.x;   // 256

    for (int idx = t; idx < HH * KK; idx += 256) {
        int i = idx / KK, k = idx % KK;
        float s = 0.f;
        for (int o = 0; o < HH; o++) s += __ldg(&fw[o]) * __ldg(&cw[(o * HH + i) * KK + k]);
        q_s[i][k] = s;
    }
    __syncthreads();
    for (int idx = t; idx < KK * HH; idx += 256) {
        int k = idx / HH, h = idx % HH;
        float s = 0.f;
        for (int i = 0; i < HH; i++) s += __ldg(&W2[h * HH + i]) * q_s[i][k];
        r_s[k][h] = s;
    }
    __syncthreads();
    for (int idx = t; idx < KK * FIN; idx += 256) {
        int k = idx / FIN, f = idx % FIN;
        float s = 0.f;
        for (int h = 0; h < HH; h++) s += __ldg(&W1[f * HH + h]) * r_s[k][h];
        d_sfk[k][f] = s;
    }
    if (t < KK) {
        float s = 0.f;
        for (int h = 0; h < HH; h++) s += __ldg(&b1[h]) * r_s[t][h];
        d_tk[t] = s;
    }
    if (t == 0) {
        float bias2 = 0.f;
        for (int i = 0; i < HH; i++)
            for (int k = 0; k < KK; k++) bias2 += q_s[i][k] * __ldg(&b2[i]);
        float C0 = __ldg(&fb[0]);
        for (int o = 0; o < HH; o++) C0 += __ldg(&fw[o]) * __ldg(&cb[o]);
        d_misc[0] = bias2;
        d_misc[1] = C0;
    }
}

// ============================================================
// Kernel 1: partial column sums of A.  Tpart[rc][m] = sum of 32 rows.
// grid (4, 128) = 512 blocks, 256 threads, float4 loads.
// ============================================================
__global__ void k1_colsum(const float* __restrict__ A) {
    const int c4 = blockIdx.x * 256 + threadIdx.x;   // float4 col index
    const int n0 = blockIdx.y * (NN / RC1);          // 32-row chunk
    const float4* Ap = reinterpret_cast<const float4*>(A);
    float4 acc = make_float4(0.f, 0.f, 0.f, 0.f);
#pragma unroll 8
    for (int n = n0; n < n0 + NN / RC1; n++) {
        float4 a = __ldg(&Ap[n * (NN / 4) + c4]);
        acc.x += a.x; acc.y += a.y; acc.z += a.z; acc.w += a.w;
    }
    *reinterpret_cast<float4*>(&d_Tpart[blockIdx.y][c4 * 4]) = acc;
}

// ============================================================
// Kernel 2: fused g + c partials.
// grid (4, 64) = 256 blocks, 256 threads. 64-row strip per block.
// Threads 0..63 build g for the strip (Tpart combine + edge rows);
// col-block 0 persists g for k4's sg reduction.
// ============================================================
__global__ void k2_cpart(const float* __restrict__ A) {
    __shared__ float gsk[KK][64];
    const int tid = threadIdx.x;
    const int c4  = blockIdx.x * 256 + tid;          // float4 col index
    const int n0  = blockIdx.y * 64;

    if (tid < 64) {
        const int n = n0 + tid;
        float T = 0.f;
#pragma unroll
        for (int r = 0; r < RC1; r++) T += d_Tpart[r][n];

        float top[4], bot[4];
#pragma unroll
        for (int j = 0; j < 4; j++) top[j] = __ldg(&A[j * NN + n]);
#pragma unroll
        for (int j = 0; j < 4; j++) bot[j] = __ldg(&A[(4092 + j) * NN + n]);

        float cumtop = 0.f;
#pragma unroll
        for (int k = 0; k < KK; k++) {
            float sb = 0.f;
#pragma unroll
            for (int j = 0; j < 4; j++) if (j >= k) sb += bot[j];
            float g = T - cumtop - sb;
            gsk[k][tid] = g;
            if (blockIdx.x == 0) d_g[k][n] = g;
            if (k < 4) cumtop += top[k];
        }
    }
    __syncthreads();

    float4 acc[KK];
#pragma unroll
    for (int k = 0; k < KK; k++) acc[k] = make_float4(0.f, 0.f, 0.f, 0.f);

    const float4* Ap = reinterpret_cast<const float4*>(A);
#pragma unroll 8
    for (int nl = 0; nl < 64; nl++) {
        float4 a = __ldg(&Ap[(n0 + nl) * (NN / 4) + c4]);
        float g0 = gsk[0][nl], g1 = gsk[1][nl], g2 = gsk[2][nl];
        float g3 = gsk[3][nl], g4 = gsk[4][nl];
        acc[0].x += a.x * g0; acc[0].y += a.y * g0; acc[0].z += a.z * g0; acc[0].w += a.w * g0;
        acc[1].x += a.x * g1; acc[1].y += a.y * g1; acc[1].z += a.z * g1; acc[1].w += a.w * g1;
        acc[2].x += a.x * g2; acc[2].y += a.y * g2; acc[2].z += a.z * g2; acc[2].w += a.w * g2;
        acc[3].x += a.x * g3; acc[3].y += a.y * g3; acc[3].z += a.z * g3; acc[3].w += a.w * g3;
        acc[4].x += a.x * g4; acc[4].y += a.y * g4; acc[4].z += a.z * g4; acc[4].w += a.w * g4;
    }
#pragma unroll
    for (int k = 0; k < KK; k++)
        *reinterpret_cast<float4*>(&d_cpart[blockIdx.y][k][c4 * 4]) = acc[k];
}

// ============================================================
// Kernel 2b: combine c partials and fold k-dim: u[m][f] = sum_k s[k][f] c_k[m].
// grid 32 blocks x 128 threads = 4096 threads (one m each).
// ============================================================
__global__ void k2b_build_u() {
    __shared__ float s_sh[KK][FIN];
    const int t = threadIdx.x;
    for (int idx = t; idx < KK * FIN; idx += 128)
        s_sh[idx / FIN][idx % FIN] = d_sfk[idx / FIN][idx % FIN];
    __syncthreads();

    const int m = blockIdx.x * 128 + t;
    float c[KK];
#pragma unroll
    for (int k = 0; k < KK; k++) {
        float s = 0.f;
#pragma unroll
        for (int r = 0; r < RC2; r++) s += d_cpart[r][k][m];
        c[k] = s;
    }

    float4* up = reinterpret_cast<float4*>(&d_u[m * FIN]);
#pragma unroll
    for (int f4 = 0; f4 < FIN / 4; f4++) {
        float4 u = make_float4(0.f, 0.f, 0.f, 0.f);
#pragma unroll
        for (int k = 0; k < KK; k++) {
            float ck = c[k];
            u.x += ck * s_sh[k][f4 * 4 + 0];
            u.y += ck * s_sh[k][f4 * 4 + 1];
            u.z += ck * s_sh[k][f4 * 4 + 2];
            u.w += ck * s_sh[k][f4 * 4 + 3];
        }
        up[f4] = u;
    }
}

// ============================================================
// Kernel 3: y[b] partials = x[b] . u   (element-wise dot, float4).
// grid (YC, BB) = 256 blocks x 256 threads; 5 float4 per thread.
// ============================================================
__global__ void k3_dot(const float* __restrict__ x) {
    const int b  = blockIdx.y;
    const int mc = blockIdx.x;
    const int t  = threadIdx.x;
    const int ub4 = mc * (NN * FIN / YC) / 4;                  // u float4 base
    const float4* xp = reinterpret_cast<const float4*>(x) + (size_t)b * (NN * FIN / 4) + ub4;
    const float4* up = reinterpret_cast<const float4*>(d_u) + ub4;

    float acc = 0.f;
#pragma unroll
    for (int i = 0; i < (NN * FIN / YC) / 4 / 256; i++) {      // 5 iters
        float4 xv = __ldg(&xp[i * 256 + t]);
        float4 uv = __ldg(&up[i * 256 + t]);
        acc += xv.x * uv.x + xv.y * uv.y + xv.z * uv.z + xv.w * uv.w;
    }

    __shared__ float red[256];
    red[t] = acc;
    __syncthreads();
    for (int ofs = 128; ofs > 0; ofs >>= 1) {
        if (t < ofs) red[t] += red[t + ofs];
        __syncthreads();
    }
    if (t == 0) d_ypart[b * YC + mc] = red[0];
}

// ============================================================
// Kernel 4: final fold.
// out[b] = (y[b] + sum_k sg_k t_k) / L + misc0 + misc1
// ============================================================
__global__ void k4_final(float* __restrict__ out) {
    __shared__ float red[256];
    __shared__ float sg_s[KK];
    const int t = threadIdx.x;   // 256

    float part[KK] = {0.f, 0.f, 0.f, 0.f, 0.f};
    for (int m = t; m < NN; m += 256) {
#pragma unroll
        for (int k = 0; k < KK; k++) part[k] += d_g[k][m];
    }
    for (int k = 0; k < KK; k++) {
        red[t] = part[k];
        __syncthreads();
        for (int ofs = 128; ofs > 0; ofs >>= 1) {
            if (t < ofs) red[t] += red[t + ofs];
            __syncthreads();
        }
        if (t == 0) sg_s[k] = red[0];
        __syncthreads();
    }

    if (t < BB) {
        float y = 0.f;
#pragma unroll
        for (int mc = 0; mc < YC; mc++) y += d_ypart[t * YC + mc];
        float gt = 0.f;
#pragma unroll
        for (int k = 0; k < KK; k++) gt += sg_s[k] * d_tk[k];
        out[t] = (y + gt) * (1.0f / (float)LL) + d_misc[0] + d_misc[1];
    }
}

// ============================================================
extern "C" void kernel_launch(void* const* d_in, const int* in_sizes, int n_in,
                              void* d_out, int out_size) {
    const float* x   = (const float*)d_in[0];
    const float* A   = (const float*)d_in[1];
    const float* W1  = (const float*)d_in[2];
    const float* b1  = (const float*)d_in[3];
    const float* W2  = (const float*)d_in[4];
    const float* b2  = (const float*)d_in[5];
    const float* cw  = (const float*)d_in[6];
    const float* cb  = (const float*)d_in[7];
    const float* fw  = (const float*)d_in[8];
    const float* fb  = (const float*)d_in[9];
    float* out = (float*)d_out;

    k0_prep<<<1, 256>>>(W1, b1, W2, b2, cw, cb, fw, fb);
    k1_colsum<<<dim3(4, RC1), 256>>>(A);
    k2_cpart<<<dim3(4, 64), 256>>>(A);
    k2b_build_u<<<32, 128>>>();
    k3_dot<<<dim3(YC, BB), 256>>>(x);
    k4_final<<<1, 256>>>(out);
}